// round 10
// baseline (speedup 1.0000x reference)
#include <cuda_runtime.h>
#include <cuda_bf16.h>

// MX quantize-dequantize: block size 32, E8M0 shared scale, E4M3 elements.
// v6: R8's winning layout (interleaved lane mapping, 2x contiguous-512B
// LDG.128 per warp per load, 8 elem/thread, dual interleaved 8-lane shfl
// reductions) + evict-first (.cs) hints on BOTH streams. The earlier .cs
// regressions were confounded with broken far-stride layouts; this is the
// clean A/B on the good pattern. Exact pow2 bit-constructed scale math.

__device__ __forceinline__ float mx_qdq_elem(float v, float inv_scale, float scale) {
    unsigned sbit = __float_as_uint(v) & 0x80000000u;
    float mag = fabsf(v) * inv_scale;          // exact pow2 multiply
    mag = fminf(mag, 448.0f);                  // E4M3 saturate
    float safe = fmaxf(mag, 0.015625f);        // 2^-6 (subnormal region -> emin)
    int e = (int)(__float_as_uint(safe) >> 23) - 127;
    float quantum = __uint_as_float((unsigned)((e - 3) + 127) << 23); // 2^(e-3)
    float invq    = __uint_as_float((unsigned)((3 - e) + 127) << 23); // 2^(3-e)
    float q = rintf(mag * invq) * quantum * scale; // round-half-even, dequant
    return __uint_as_float(__float_as_uint(q) | sbit);
}

__device__ __forceinline__ float amax4(const float4& a) {
    return fmaxf(fmaxf(fabsf(a.x), fabsf(a.y)), fmaxf(fabsf(a.z), fabsf(a.w)));
}

__device__ __forceinline__ void scales_from_amax(float m, float& scale, float& inv_scale) {
    // shared_exp = floor(log2(amax)) - 8, exact via exponent-field extract;
    // clamp keeps the bit-constructed pow2 floats normal. amax==0 -> all
    // elements are zero -> scale value irrelevant.
    int se = ((int)(__float_as_uint(m) >> 23) - 127) - 8;
    se = max(se, -126);
    scale     = __uint_as_float((unsigned)(se + 127) << 23);
    inv_scale = __uint_as_float((unsigned)(127 - se) << 23);
}

__device__ __forceinline__ float4 qdq4(const float4& a, float inv_scale, float scale) {
    float4 o;
    o.x = mx_qdq_elem(a.x, inv_scale, scale);
    o.y = mx_qdq_elem(a.y, inv_scale, scale);
    o.z = mx_qdq_elem(a.z, inv_scale, scale);
    o.w = mx_qdq_elem(a.w, inv_scale, scale);
    return o;
}

__global__ void __launch_bounds__(256)
mx_qdq_kernel(const float4* __restrict__ x, float4* __restrict__ y, int nvec) {
    int t    = blockIdx.x * blockDim.x + threadIdx.x;
    int lane = t & 31;
    int warp = t >> 5;
    int base = warp * 64;          // warp window: 64 consecutive float4 (1KB)
    int i0 = base + lane;          // load A: contiguous 512B across the warp
    int i1 = base + 32 + lane;     // load B: next contiguous 512B

    if (i1 >= nvec) {
        if (i0 < nvec) {
            float4 a = __ldcs(&x[i0]);
            float m = amax4(a);
            m = fmaxf(m, __shfl_xor_sync(0xffffffffu, m, 1));
            m = fmaxf(m, __shfl_xor_sync(0xffffffffu, m, 2));
            m = fmaxf(m, __shfl_xor_sync(0xffffffffu, m, 4));
            float s, is; scales_from_amax(m, s, is);
            float4 o = qdq4(a, is, s);
            __stcs(&y[i0], o);
        }
        return;
    }

    float4 a = __ldcs(&x[i0]);
    float4 b = __ldcs(&x[i1]);

    float mA = amax4(a);
    float mB = amax4(b);

    // Two independent 8-lane reductions (lanes 8k..8k+7 share one MX block
    // for each load); interleave so SHFL latency overlaps.
    float tA = __shfl_xor_sync(0xffffffffu, mA, 1);
    float tB = __shfl_xor_sync(0xffffffffu, mB, 1);
    mA = fmaxf(mA, tA);
    mB = fmaxf(mB, tB);
    tA = __shfl_xor_sync(0xffffffffu, mA, 2);
    tB = __shfl_xor_sync(0xffffffffu, mB, 2);
    mA = fmaxf(mA, tA);
    mB = fmaxf(mB, tB);
    tA = __shfl_xor_sync(0xffffffffu, mA, 4);
    tB = __shfl_xor_sync(0xffffffffu, mB, 4);
    mA = fmaxf(mA, tA);
    mB = fmaxf(mB, tB);

    float sA, isA, sB, isB;
    scales_from_amax(mA, sA, isA);
    scales_from_amax(mB, sB, isB);

    float4 oa = qdq4(a, isA, sA);
    float4 ob = qdq4(b, isB, sB);
    __stcs(&y[i0], oa);
    __stcs(&y[i1], ob);
}

extern "C" void kernel_launch(void* const* d_in, const int* in_sizes, int n_in,
                              void* d_out, int out_size) {
    const float* x = (const float*)d_in[0];
    float*       y = (float*)d_out;
    int n    = in_sizes[0];        // 33,554,432 (divisible by 32)
    int nvec = n / 4;              // 8,388,608 float4
    int nthreads = nvec / 2;       // 8 elements per thread
    int block = 256;
    int grid  = (nthreads + block - 1) / block;  // 16384
    mx_qdq_kernel<<<grid, block>>>((const float4*)x, (float4*)y, nvec);
}